// round 7
// baseline (speedup 1.0000x reference)
#include <cuda_runtime.h>

// Problem constants (fixed by the reference setup)
#define DE   200          // entity / output dim
#define DR   200          // relation dim
#define DIN  400          // DE + DR
#define NB   4            // num bases
#define KTOT (NB * DIN)   // 1600 rows of the collapsed matvec

#define NBLK 148          // one wave
#define NTHR 512
#define NMM  37           // consumer (matvec) blocks: blockIdx 0..36
#define NSCAN (NBLK - NMM)          // 111 scan blocks: blockIdx 37..147
#define KCH  44           // k-rows per consumer block (37*44 = 1628 >= 1600)
#define KPG  22           // k-rows per thread-group (2 groups x 256 threads)
#define CAP  4096         // match-slot capacity (expected ~8)
#define READY_TARGET (NSCAN + 1)    // 111 scan arrivals + block0 out-zero

// persistent scratch (static device globals — no allocation).
// All counters/flags are reset by the LAST block to finish, so every graph
// replay starts from the identical state.
__device__ int    g_reserve;        // match slot allocator (true match count)
__device__ int    g_ready_all;      // scan-done arrivals + block0's out-zero
__device__ int    g_done;           // completion counter (for reset)
__device__ int    g_flag[CAP];      // per-slot "meta ready" flags
__device__ int    g_nid[CAP];
__device__ int    g_ri[CAP];
__device__ float4 g_att[CAP];

__global__ void __launch_bounds__(NTHR, 1)
fused_kernel(const float* __restrict__ ent,
             const float* __restrict__ relemb,
             const float* __restrict__ basis,
             const float* __restrict__ att,
             const int*   __restrict__ node_id,
             const int*   __restrict__ edge_src,
             const int*   __restrict__ edge_dst,
             const int*   __restrict__ edge_type,
             const int*   __restrict__ rel_index,
             const int*   __restrict__ u_ptr,
             float* __restrict__ out,
             int E) {
    const int tid = threadIdx.x;
    __shared__ int s_last;

    if (blockIdx.x >= NMM) {
        // ───────────────────────── scan block ─────────────────────────
        // Publish a match: reserve slot -> write meta -> fence -> set flag.
        auto found = [&](int e) {
            int p = atomicAdd(&g_reserve, 1);
            if (p < CAP) {
                int s  = __ldcg(&edge_src[e]);
                int ri = __ldcg(&rel_index[e]);
                int ty = __ldcg(&edge_type[e]);
                g_nid[p] = __ldcg(&node_id[s]);
                g_ri[p]  = ri;
                g_att[p] = __ldcg((const float4*)(att + (size_t)ty * NB));
                __threadfence();
                *(volatile int*)&g_flag[p] = 1;
            }
        };
        const int sgt = (blockIdx.x - NMM) * NTHR + tid;
        const int SGT = NSCAN * NTHR;
        const int u   = *u_ptr;                 // L1-cached broadcast
        const int nv  = E >> 2;
        const int4* ed4 = (const int4*)edge_dst;
        for (int i = sgt; i < nv; i += 2 * SGT) {   // exactly 1 iter at these sizes
            int  i2 = i + SGT;
            bool h2 = i2 < nv;
            int4 v1 = __ldcg(&ed4[i]);
            int4 v2;
            if (h2) v2 = __ldcg(&ed4[i2]);
            int b1 = i << 2;
            if (v1.x == u) found(b1 + 0);
            if (v1.y == u) found(b1 + 1);
            if (v1.z == u) found(b1 + 2);
            if (v1.w == u) found(b1 + 3);
            if (h2) {
                int b2 = i2 << 2;
                if (v2.x == u) found(b2 + 0);
                if (v2.y == u) found(b2 + 1);
                if (v2.z == u) found(b2 + 2);
                if (v2.w == u) found(b2 + 3);
            }
        }
        for (int e = (nv << 2) + sgt; e < E; e += SGT) {   // scalar tail
            if (__ldcg(&edge_dst[e]) == u) found(e);
        }
        __syncthreads();
        if (tid == 0) { __threadfence(); atomicAdd(&g_ready_all, 1); }
    } else {
        // ──────────────────────── consumer block ────────────────────────
        const int k0   = blockIdx.x * KCH;
        const int kmax = (KTOT - k0) < KCH ? (KTOT - k0) : KCH;
        const int g    = tid >> 8;       // 0 or 1
        const int o    = tid & 255;      // output index within group

        __shared__ float sy[KCH];
        __shared__ float s1[DE];
        __shared__ int   s_sd, s_r;

        // block 0 zeroes the REDG target, then arrives (orders zero < REDGs)
        if (blockIdx.x == 0) {
            if (tid < DE) out[tid] = 0.0f;
            __syncthreads();
            if (tid == 0) { __threadfence(); atomicAdd(&g_ready_all, 1); }
        }

        // prefetch this block's basis chunk into registers (overlaps scan)
        float breg[KPG];
        if (o < DE) {
            #pragma unroll
            for (int j = 0; j < KPG; j++) {
                int kk = g * KPG + j;
                breg[j] = (kk < kmax) ? __ldcg(&basis[(size_t)(k0 + kk) * DE + o]) : 0.0f;
            }
        }
        if (tid < KCH) sy[tid] = 0.0f;
        __syncthreads();

        // streaming consume loop: process matches in parallel batches as
        // they are published, while the scan is still in flight.
        int processed = 0;
        int final_r   = 0;
        while (true) {
            if (tid == 0) {
                int sd, r;
                while (true) {
                    sd = *(volatile int*)&g_ready_all;
                    r  = *(volatile int*)&g_reserve;
                    if (r > processed || sd == READY_TARGET) break;
                }
                s_sd = sd; s_r = r;
            }
            __syncthreads();
            int rc        = s_r < CAP ? s_r : CAP;
            int batch_end = rc < processed + NTHR ? rc : processed + NTHR;
            int bs        = batch_end - processed;
            if (bs > 0) {
                if (tid < bs) {
                    while (*(volatile int*)&g_flag[processed + tid] == 0) { }
                    __threadfence();     // acquire: meta visible
                }
                __syncthreads();
                for (int p = tid; p < bs * kmax; p += NTHR) {
                    int mm = p / kmax;
                    int kk = p - mm * kmax;
                    int m  = processed + mm;
                    int k  = k0 + kk;
                    int b  = k / DIN;
                    int i  = k - b * DIN;
                    float x = (i < DE)
                        ? __ldcg(&ent[(size_t)g_nid[m] * DE + i])
                        : __ldcg(&relemb[(size_t)g_ri[m] * DR + (i - DE)]);
                    float a = ((const float*)&g_att[m])[b];
                    atomicAdd(&sy[kk], a * x);
                }
                processed = batch_end;
            }
            if (s_sd == READY_TARGET && processed >= (s_r < CAP ? s_r : CAP)) {
                final_r = s_r;           // true (uncapped) match count
                break;
            }
            __syncthreads();             // WAR: before tid0 rewrites s_sd/s_r
        }
        __syncthreads();

        // combine halves in smem -> ONE REDG lane per output element
        const float inv = 1.0f / fmaxf((float)final_r, 1.0f);
        float acc = 0.0f;
        if (o < DE) {
            #pragma unroll
            for (int j = 0; j < KPG; j++) acc += sy[g * KPG + j] * breg[j];
            if (g == 1) s1[o] = acc;
        }
        __syncthreads();
        if (o < DE && g == 0 && final_r > 0) {
            atomicAdd(&out[o], (acc + s1[o]) * inv);   // fire-and-forget REDG
        }
    }

    // ── Tail: last block to finish resets scratch (parallel, no spin) ──
    __syncthreads();
    if (tid == 0) {
        __threadfence();
        int a = atomicAdd(&g_done, 1);
        s_last = (a == NBLK - 1) ? 1 : 0;
    }
    __syncthreads();
    if (s_last) {
        int rc = *(volatile int*)&g_reserve;
        if (rc > CAP) rc = CAP;
        for (int m = tid; m < rc; m += NTHR) g_flag[m] = 0;
        if (tid == 0) { g_reserve = 0; g_ready_all = 0; g_done = 0; }
    }
}

extern "C" void kernel_launch(void* const* d_in, const int* in_sizes, int n_in,
                              void* d_out, int out_size) {
    const float* ent    = (const float*)d_in[0];  // [100000, 200]
    const float* relemb = (const float*)d_in[1];  // [200, 200]
    const float* basis  = (const float*)d_in[2];  // [4, 400, 200]
    const float* att    = (const float*)d_in[3];  // [400, 4]
    const int* node_id  = (const int*)d_in[4];    // [50000]
    const int* edge_src = (const int*)d_in[5];    // [400000]
    const int* edge_dst = (const int*)d_in[6];    // [400000]
    const int* edge_typ = (const int*)d_in[7];    // [400000]
    const int* rel_idx  = (const int*)d_in[8];    // [400000]
    const int* u_ptr    = (const int*)d_in[9];    // scalar
    float* out = (float*)d_out;                   // [200]

    int E = in_sizes[6];

    fused_kernel<<<NBLK, NTHR>>>(ent, relemb, basis, att,
                                 node_id, edge_src, edge_dst, edge_typ, rel_idx,
                                 u_ptr, out, E);
}